// round 1
// baseline (speedup 1.0000x reference)
#include <cuda_runtime.h>
#include <math.h>

#define NBLK 128
#define TPB  256
typedef unsigned long long ull;

// ---------------- device scratch (static, no allocation) ----------------
__device__ float g_h1[2][256 * 256];
__device__ float g_h2[2][256 * 256];
__device__ float g_last[256 * 256];
__device__ float g_y[256 * 256];
__device__ float g_emb[256 * 256 * 8];   // [t][b][e]
__device__ unsigned g_bar;

struct SmemLayout {
    float Wh0[256 * 32];   // [k][c] c = unit*4 + gate (8 units, 4 gates)
    float Wi1[256 * 32];
    float Wh1[256 * 32];
    float Wi0[8 * 32];     // [e][c]
    float b0[32];
    float b1[32];
    float hs[256 * 64];    // staged h, [k][b_local]
};

// ---------------- packed f32x2 helpers ----------------
__device__ __forceinline__ ull pk(float a, float b) {
    ull r; asm("mov.b64 %0, {%1,%2};" : "=l"(r) : "f"(a), "f"(b)); return r;
}
__device__ __forceinline__ void unpk(ull v, float& a, float& b) {
    asm("mov.b64 {%0,%1}, %2;" : "=f"(a), "=f"(b) : "l"(v));
}
__device__ __forceinline__ void fma2(ull& acc, ull a, ull b) {
    asm("fma.rn.f32x2 %0, %1, %2, %0;" : "+l"(acc) : "l"(a), "l"(b));
}

__device__ __forceinline__ float sigf(float x) { return 1.f / (1.f + __expf(-x)); }
__device__ __forceinline__ float tanha(float x) { return 2.f * sigf(2.f * x) - 1.f; }

// ---------------- grid-wide barrier (persistent kernel) ----------------
__device__ __forceinline__ void grid_sync(unsigned& gen) {
    __syncthreads();
    if (threadIdx.x == 0) {
        __threadfence();               // release all block writes (cumulative)
        atomicAdd(&g_bar, 1u);
        gen += NBLK;
        unsigned v;
        do {
            asm volatile("ld.acquire.gpu.global.u32 %0, [%1];" : "=r"(v) : "l"(&g_bar));
        } while (v < gen);
    }
    __syncthreads();
}

// ---------------- h staging: global [b][k] -> smem [k][b_local] ----------------
__device__ __forceinline__ void stage_h(const float* __restrict__ src,
                                        float* __restrict__ hs, int bg, int tid) {
    int bl = tid & 63;
    int kg = tid >> 6;  // 0..3
    const float4* s = (const float4*)(src + (bg * 64 + bl) * 256) + kg * 16;
#pragma unroll 4
    for (int kk = 0; kk < 16; kk++) {
        float4 v = s[kk];
        int k = (kg * 16 + kk) * 4;
        hs[(k + 0) * 64 + bl] = v.x;
        hs[(k + 1) * 64 + bl] = v.y;
        hs[(k + 2) * 64 + bl] = v.z;
        hs[(k + 3) * 64 + bl] = v.w;
    }
}

// ---------------- tile GEMM accumulate: acc += W^T slice * h ----------------
// Thread owns unit txc (4 gate cols) x 2 batch rows (2*txb, 2*txb+1).
__device__ __forceinline__ void gemm_acc(const float* __restrict__ sW,
                                         const float* __restrict__ hs,
                                         int txc, int txb,
                                         ull& A00, ull& A01, ull& A10, ull& A11) {
    const float* wp = sW + 4 * txc;
    const float* hp = hs + 2 * txb;
#pragma unroll 4
    for (int k = 0; k < 256; k++) {
        ull w01 = *(const ull*)(wp + k * 32);
        ull w23 = *(const ull*)(wp + k * 32 + 2);
        float2 h = *(const float2*)(hp + k * 64);
        ull hd0 = pk(h.x, h.x);
        ull hd1 = pk(h.y, h.y);
        fma2(A00, w01, hd0);
        fma2(A01, w23, hd0);
        fma2(A10, w01, hd1);
        fma2(A11, w23, hd1);
    }
}

// ---------------- prep: embedding gather + barrier reset ----------------
__global__ void prep_kernel(const int* __restrict__ tokens,
                            const float* __restrict__ emb) {
    int idx = blockIdx.x * 256 + threadIdx.x;  // 0..65535
    if (idx == 0) g_bar = 0;
    int b = idx >> 8, t = idx & 255;
    int tok = tokens[b * 256 + t];
    const float4* e = (const float4*)(emb + tok * 8);
    float4* d = (float4*)(g_emb + (t * 256 + b) * 8);
    d[0] = e[0];
    d[1] = e[1];
}

// ---------------- persistent LSTM kernel ----------------
extern __shared__ float smem_raw[];

__global__ void __launch_bounds__(TPB, 1)
lstm_kernel(const int* __restrict__ lengths,
            const float* __restrict__ w_ih0, const float* __restrict__ w_hh0,
            const float* __restrict__ b_ih0, const float* __restrict__ b_hh0,
            const float* __restrict__ w_ih1, const float* __restrict__ w_hh1,
            const float* __restrict__ b_ih1, const float* __restrict__ b_hh1,
            const float* __restrict__ ff_w, const float* __restrict__ ff_b,
            const float* __restrict__ bn_g, const float* __restrict__ bn_b,
            float* __restrict__ out) {
    SmemLayout* S = (SmemLayout*)smem_raw;
    const int tid = threadIdx.x;
    const int bid = blockIdx.x;
    const int bg = bid >> 5;   // batch group 0..3  (64 rows)
    const int ug = bid & 31;   // unit group 0..31  (8 units)
    const int txc = tid & 7;   // unit within group
    const int txb = tid >> 3;  // 0..31 -> rows 2*txb, 2*txb+1
    const int b0 = bg * 64 + 2 * txb, b1 = b0 + 1;
    const int u = ug * 8 + txc;

    // --- load + permute weights into SMEM: Wt[k][c], c = uu*4 + gate ---
    for (int idx = tid; idx < 32 * 256; idx += TPB) {
        int c = idx & 31, k = idx >> 5;
        int uu = c >> 2, g = c & 3;
        int row = g * 256 + ug * 8 + uu;
        S->Wh0[k * 32 + c] = w_hh0[row * 256 + k];
        S->Wi1[k * 32 + c] = w_ih1[row * 256 + k];
        S->Wh1[k * 32 + c] = w_hh1[row * 256 + k];
    }
    for (int idx = tid; idx < 8 * 32; idx += TPB) {
        int c = idx & 31, e = idx >> 5;
        int uu = c >> 2, g = c & 3;
        int row = g * 256 + ug * 8 + uu;
        S->Wi0[e * 32 + c] = w_ih0[row * 8 + e];
    }
    if (tid < 32) {
        int uu = tid >> 2, g = tid & 3;
        int row = g * 256 + ug * 8 + uu;
        S->b0[tid] = b_ih0[row] + b_hh0[row];
        S->b1[tid] = b_ih1[row] + b_hh1[row];
    }
    // zero initial h buffers (each block zeroes its own tile of buffer 0)
    g_h1[0][b0 * 256 + u] = 0.f;
    g_h1[0][b1 * 256 + u] = 0.f;
    g_h2[0][b0 * 256 + u] = 0.f;
    g_h2[0][b1 * 256 + u] = 0.f;

    const int len0 = lengths[b0], len1 = lengths[b1];
    float c1x = 0.f, c1y = 0.f, c2x = 0.f, c2y = 0.f;
    unsigned gen = 0;
    grid_sync(gen);

    for (int t = 0; t < 256; t++) {
        const int pb = t & 1, nb = pb ^ 1;

        // ================= layer 0 =================
        stage_h(g_h1[pb], S->hs, bg, tid);
        __syncthreads();

        float i0, f0, g0v, o0, i1, f1, g1v, o1;
        {
            float a0[4], a1[4];
#pragma unroll
            for (int j = 0; j < 4; j++) { a0[j] = S->b0[4 * txc + j]; a1[j] = a0[j]; }
            const float* e0 = &g_emb[(t * 256 + b0) * 8];
            const float* e1 = &g_emb[(t * 256 + b1) * 8];
#pragma unroll
            for (int e = 0; e < 8; e++) {
                float x0 = e0[e], x1 = e1[e];
#pragma unroll
                for (int j = 0; j < 4; j++) {
                    float w = S->Wi0[e * 32 + 4 * txc + j];
                    a0[j] += x0 * w;
                    a1[j] += x1 * w;
                }
            }
            ull A00 = pk(a0[0], a0[1]), A01 = pk(a0[2], a0[3]);
            ull A10 = pk(a1[0], a1[1]), A11 = pk(a1[2], a1[3]);
            gemm_acc(S->Wh0, S->hs, txc, txb, A00, A01, A10, A11);
            unpk(A00, i0, f0); unpk(A01, g0v, o0);
            unpk(A10, i1, f1); unpk(A11, g1v, o1);
        }
        c1x = sigf(f0) * c1x + sigf(i0) * tanha(g0v);
        float h1a = sigf(o0) * tanha(c1x);
        c1y = sigf(f1) * c1y + sigf(i1) * tanha(g1v);
        float h1b = sigf(o1) * tanha(c1y);
        g_h1[nb][b0 * 256 + u] = h1a;
        g_h1[nb][b1 * 256 + u] = h1b;
        grid_sync(gen);

        // ================= layer 1 =================
        stage_h(g_h1[nb], S->hs, bg, tid);
        __syncthreads();
        ull A00 = pk(S->b1[4 * txc + 0], S->b1[4 * txc + 1]);
        ull A01 = pk(S->b1[4 * txc + 2], S->b1[4 * txc + 3]);
        ull A10 = A00, A11 = A01;
        gemm_acc(S->Wi1, S->hs, txc, txb, A00, A01, A10, A11);
        __syncthreads();
        stage_h(g_h2[pb], S->hs, bg, tid);
        __syncthreads();
        gemm_acc(S->Wh1, S->hs, txc, txb, A00, A01, A10, A11);

        unpk(A00, i0, f0); unpk(A01, g0v, o0);
        unpk(A10, i1, f1); unpk(A11, g1v, o1);
        c2x = sigf(f0) * c2x + sigf(i0) * tanha(g0v);
        float h2a = sigf(o0) * tanha(c2x);
        c2y = sigf(f1) * c2y + sigf(i1) * tanha(g1v);
        float h2b = sigf(o1) * tanha(c2y);
        g_h2[nb][b0 * 256 + u] = h2a;
        g_h2[nb][b1 * 256 + u] = h2b;
        if (t == len0 - 1) g_last[b0 * 256 + u] = h2a;
        if (t == len1 - 1) g_last[b1 * 256 + u] = h2b;
        grid_sync(gen);
    }

    // ================= y = relu(last) @ ff_w^T + ff_b =================
    // block handles batch rows 2*bid, 2*bid+1; thread = output column
    for (int r = 0; r < 2; r++) {
        int b = 2 * bid + r;
        S->hs[tid] = fmaxf(g_last[b * 256 + tid], 0.f);
        __syncthreads();
        float acc = ff_b[tid];
        const float4* wr = (const float4*)(ff_w + tid * 256);
#pragma unroll 4
        for (int k4 = 0; k4 < 64; k4++) {
            float4 w = wr[k4];
            const float* h4 = &S->hs[4 * k4];
            acc += w.x * h4[0] + w.y * h4[1] + w.z * h4[2] + w.w * h4[3];
        }
        g_y[b * 256 + tid] = acc;
        __syncthreads();
    }
    grid_sync(gen);

    // ================= BatchNorm over batch axis =================
    // block handles columns 2*bid, 2*bid+1; thread = batch row
    float* red = S->hs;
    for (int r = 0; r < 2; r++) {
        int j = 2 * bid + r;
        float v = g_y[tid * 256 + j];
        red[tid] = v;
        __syncthreads();
        for (int s = 128; s > 0; s >>= 1) {
            if (tid < s) red[tid] += red[tid + s];
            __syncthreads();
        }
        float mean = red[0] * (1.f / 256.f);
        __syncthreads();
        float d = v - mean;
        red[tid] = d * d;
        __syncthreads();
        for (int s = 128; s > 0; s >>= 1) {
            if (tid < s) red[tid] += red[tid + s];
            __syncthreads();
        }
        float var = red[0] * (1.f / 256.f);
        __syncthreads();
        out[tid * 256 + j] = bn_g[j] * d * rsqrtf(var + 1e-5f) + bn_b[j];
    }
}

// ---------------- launch ----------------
extern "C" void kernel_launch(void* const* d_in, const int* in_sizes, int n_in,
                              void* d_out, int out_size) {
    const int*   tokens    = (const int*)d_in[0];
    const int*   lengths   = (const int*)d_in[1];
    const float* embedding = (const float*)d_in[2];
    const float* w_ih0     = (const float*)d_in[3];
    const float* w_hh0     = (const float*)d_in[4];
    const float* b_ih0     = (const float*)d_in[5];
    const float* b_hh0     = (const float*)d_in[6];
    const float* w_ih1     = (const float*)d_in[7];
    const float* w_hh1     = (const float*)d_in[8];
    const float* b_ih1     = (const float*)d_in[9];
    const float* b_hh1     = (const float*)d_in[10];
    const float* ff_w      = (const float*)d_in[11];
    const float* ff_b      = (const float*)d_in[12];
    const float* bn_g      = (const float*)d_in[13];
    const float* bn_b      = (const float*)d_in[14];
    float* out = (float*)d_out;

    cudaFuncSetAttribute(lstm_kernel, cudaFuncAttributeMaxDynamicSharedMemorySize,
                         (int)sizeof(SmemLayout));

    prep_kernel<<<256, 256>>>(tokens, embedding);
    lstm_kernel<<<NBLK, TPB, sizeof(SmemLayout)>>>(
        lengths, w_ih0, w_hh0, b_ih0, b_hh0,
        w_ih1, w_hh1, b_ih1, b_hh1,
        ff_w, ff_b, bn_g, bn_b, out);
}

// round 2
// speedup vs baseline: 1.0022x; 1.0022x over previous
#include <cuda_runtime.h>
#include <math.h>

#define NBLK 128
#define TPB  256
typedef unsigned long long ull;

// ---------------- device scratch (static, no allocation) ----------------
__device__ float g_h1[2][256 * 256];
__device__ float g_h2[2][256 * 256];
__device__ float g_last[256 * 256];
__device__ float g_y[256 * 256];
__device__ float g_emb[256 * 256 * 8];   // [t][b][e]
__device__ unsigned g_bar;

struct SmemLayout {
    float Wh0[256 * 32];   // [k][c] c = unit*4 + gate (8 units, 4 gates)
    float Wi1[256 * 32];
    float Wh1[256 * 32];
    float Wi0[8 * 32];     // [e][c]
    float b0[32];
    float b1[32];
    float hs[256 * 64];    // staged h, [k][b_local]
};

// ---------------- packed f32x2 helpers ----------------
__device__ __forceinline__ ull pk(float a, float b) {
    ull r; asm("mov.b64 %0, {%1,%2};" : "=l"(r) : "f"(a), "f"(b)); return r;
}
__device__ __forceinline__ void unpk(ull v, float& a, float& b) {
    asm("mov.b64 {%0,%1}, %2;" : "=f"(a), "=f"(b) : "l"(v));
}
__device__ __forceinline__ void fma2(ull& acc, ull a, ull b) {
    asm("fma.rn.f32x2 %0, %1, %2, %0;" : "+l"(acc) : "l"(a), "l"(b));
}

__device__ __forceinline__ float sigf(float x) { return 1.f / (1.f + __expf(-x)); }
__device__ __forceinline__ float tanha(float x) { return 2.f * sigf(2.f * x) - 1.f; }

// ---------------- grid-wide barrier (persistent kernel) ----------------
__device__ __forceinline__ void grid_sync(unsigned& gen) {
    __syncthreads();
    if (threadIdx.x == 0) {
        __threadfence();               // release all block writes (cumulative)
        atomicAdd(&g_bar, 1u);
        gen += NBLK;
        unsigned v;
        do {
            asm volatile("ld.acquire.gpu.global.u32 %0, [%1];" : "=r"(v) : "l"(&g_bar));
        } while (v < gen);
    }
    __syncthreads();
}

// ---------------- h staging: global [b][k] -> smem [k][b_local] ----------------
__device__ __forceinline__ void stage_h(const float* __restrict__ src,
                                        float* __restrict__ hs, int bg, int tid) {
    int bl = tid & 63;
    int kg = tid >> 6;  // 0..3
    const float4* s = (const float4*)(src + (bg * 64 + bl) * 256) + kg * 16;
#pragma unroll 4
    for (int kk = 0; kk < 16; kk++) {
        float4 v = s[kk];
        int k = (kg * 16 + kk) * 4;
        hs[(k + 0) * 64 + bl] = v.x;
        hs[(k + 1) * 64 + bl] = v.y;
        hs[(k + 2) * 64 + bl] = v.z;
        hs[(k + 3) * 64 + bl] = v.w;
    }
}

// ---------------- tile GEMM accumulate: acc += W^T slice * h ----------------
// Thread owns unit txc (4 gate cols) x 2 batch rows (2*txb, 2*txb+1).
__device__ __forceinline__ void gemm_acc(const float* __restrict__ sW,
                                         const float* __restrict__ hs,
                                         int txc, int txb,
                                         ull& A00, ull& A01, ull& A10, ull& A11) {
    const float* wp = sW + 4 * txc;
    const float* hp = hs + 2 * txb;
#pragma unroll 4
    for (int k = 0; k < 256; k++) {
        ull w01 = *(const ull*)(wp + k * 32);
        ull w23 = *(const ull*)(wp + k * 32 + 2);
        float2 h = *(const float2*)(hp + k * 64);
        ull hd0 = pk(h.x, h.x);
        ull hd1 = pk(h.y, h.y);
        fma2(A00, w01, hd0);
        fma2(A01, w23, hd0);
        fma2(A10, w01, hd1);
        fma2(A11, w23, hd1);
    }
}

// ---------------- prep: embedding gather + barrier reset ----------------
__global__ void prep_kernel(const int* __restrict__ tokens,
                            const float* __restrict__ emb) {
    int idx = blockIdx.x * 256 + threadIdx.x;  // 0..65535
    if (idx == 0) g_bar = 0;
    int b = idx >> 8, t = idx & 255;
    int tok = tokens[b * 256 + t];
    const float4* e = (const float4*)(emb + tok * 8);
    float4* d = (float4*)(g_emb + (t * 256 + b) * 8);
    d[0] = e[0];
    d[1] = e[1];
}

// ---------------- persistent LSTM kernel ----------------
extern __shared__ float smem_raw[];

__global__ void __launch_bounds__(TPB, 1)
lstm_kernel(const int* __restrict__ lengths,
            const float* __restrict__ w_ih0, const float* __restrict__ w_hh0,
            const float* __restrict__ b_ih0, const float* __restrict__ b_hh0,
            const float* __restrict__ w_ih1, const float* __restrict__ w_hh1,
            const float* __restrict__ b_ih1, const float* __restrict__ b_hh1,
            const float* __restrict__ ff_w, const float* __restrict__ ff_b,
            const float* __restrict__ bn_g, const float* __restrict__ bn_b,
            float* __restrict__ out) {
    SmemLayout* S = (SmemLayout*)smem_raw;
    const int tid = threadIdx.x;
    const int bid = blockIdx.x;
    const int bg = bid >> 5;   // batch group 0..3  (64 rows)
    const int ug = bid & 31;   // unit group 0..31  (8 units)
    const int txc = tid & 7;   // unit within group
    const int txb = tid >> 3;  // 0..31 -> rows 2*txb, 2*txb+1
    const int b0 = bg * 64 + 2 * txb, b1 = b0 + 1;
    const int u = ug * 8 + txc;

    // --- load + permute weights into SMEM: Wt[k][c], c = uu*4 + gate ---
    for (int idx = tid; idx < 32 * 256; idx += TPB) {
        int c = idx & 31, k = idx >> 5;
        int uu = c >> 2, g = c & 3;
        int row = g * 256 + ug * 8 + uu;
        S->Wh0[k * 32 + c] = w_hh0[row * 256 + k];
        S->Wi1[k * 32 + c] = w_ih1[row * 256 + k];
        S->Wh1[k * 32 + c] = w_hh1[row * 256 + k];
    }
    for (int idx = tid; idx < 8 * 32; idx += TPB) {
        int c = idx & 31, e = idx >> 5;
        int uu = c >> 2, g = c & 3;
        int row = g * 256 + ug * 8 + uu;
        S->Wi0[e * 32 + c] = w_ih0[row * 8 + e];
    }
    if (tid < 32) {
        int uu = tid >> 2, g = tid & 3;
        int row = g * 256 + ug * 8 + uu;
        S->b0[tid] = b_ih0[row] + b_hh0[row];
        S->b1[tid] = b_ih1[row] + b_hh1[row];
    }
    // zero initial h buffers (each block zeroes its own tile of buffer 0)
    g_h1[0][b0 * 256 + u] = 0.f;
    g_h1[0][b1 * 256 + u] = 0.f;
    g_h2[0][b0 * 256 + u] = 0.f;
    g_h2[0][b1 * 256 + u] = 0.f;

    const int len0 = lengths[b0], len1 = lengths[b1];
    float c1x = 0.f, c1y = 0.f, c2x = 0.f, c2y = 0.f;
    unsigned gen = 0;
    grid_sync(gen);

    for (int t = 0; t < 256; t++) {
        const int pb = t & 1, nb = pb ^ 1;

        // ================= layer 0 =================
        stage_h(g_h1[pb], S->hs, bg, tid);
        __syncthreads();

        float i0, f0, g0v, o0, i1, f1, g1v, o1;
        {
            float a0[4], a1[4];
#pragma unroll
            for (int j = 0; j < 4; j++) { a0[j] = S->b0[4 * txc + j]; a1[j] = a0[j]; }
            const float* e0 = &g_emb[(t * 256 + b0) * 8];
            const float* e1 = &g_emb[(t * 256 + b1) * 8];
#pragma unroll
            for (int e = 0; e < 8; e++) {
                float x0 = e0[e], x1 = e1[e];
#pragma unroll
                for (int j = 0; j < 4; j++) {
                    float w = S->Wi0[e * 32 + 4 * txc + j];
                    a0[j] += x0 * w;
                    a1[j] += x1 * w;
                }
            }
            ull A00 = pk(a0[0], a0[1]), A01 = pk(a0[2], a0[3]);
            ull A10 = pk(a1[0], a1[1]), A11 = pk(a1[2], a1[3]);
            gemm_acc(S->Wh0, S->hs, txc, txb, A00, A01, A10, A11);
            unpk(A00, i0, f0); unpk(A01, g0v, o0);
            unpk(A10, i1, f1); unpk(A11, g1v, o1);
        }
        c1x = sigf(f0) * c1x + sigf(i0) * tanha(g0v);
        float h1a = sigf(o0) * tanha(c1x);
        c1y = sigf(f1) * c1y + sigf(i1) * tanha(g1v);
        float h1b = sigf(o1) * tanha(c1y);
        g_h1[nb][b0 * 256 + u] = h1a;
        g_h1[nb][b1 * 256 + u] = h1b;
        grid_sync(gen);

        // ================= layer 1 =================
        stage_h(g_h1[nb], S->hs, bg, tid);
        __syncthreads();
        ull A00 = pk(S->b1[4 * txc + 0], S->b1[4 * txc + 1]);
        ull A01 = pk(S->b1[4 * txc + 2], S->b1[4 * txc + 3]);
        ull A10 = A00, A11 = A01;
        gemm_acc(S->Wi1, S->hs, txc, txb, A00, A01, A10, A11);
        __syncthreads();
        stage_h(g_h2[pb], S->hs, bg, tid);
        __syncthreads();
        gemm_acc(S->Wh1, S->hs, txc, txb, A00, A01, A10, A11);

        unpk(A00, i0, f0); unpk(A01, g0v, o0);
        unpk(A10, i1, f1); unpk(A11, g1v, o1);
        c2x = sigf(f0) * c2x + sigf(i0) * tanha(g0v);
        float h2a = sigf(o0) * tanha(c2x);
        c2y = sigf(f1) * c2y + sigf(i1) * tanha(g1v);
        float h2b = sigf(o1) * tanha(c2y);
        g_h2[nb][b0 * 256 + u] = h2a;
        g_h2[nb][b1 * 256 + u] = h2b;
        if (t == len0 - 1) g_last[b0 * 256 + u] = h2a;
        if (t == len1 - 1) g_last[b1 * 256 + u] = h2b;
        grid_sync(gen);
    }

    // ================= y = relu(last) @ ff_w^T + ff_b =================
    // block handles batch rows 2*bid, 2*bid+1; thread = output column
    for (int r = 0; r < 2; r++) {
        int b = 2 * bid + r;
        S->hs[tid] = fmaxf(g_last[b * 256 + tid], 0.f);
        __syncthreads();
        float acc = ff_b[tid];
        const float4* wr = (const float4*)(ff_w + tid * 256);
#pragma unroll 4
        for (int k4 = 0; k4 < 64; k4++) {
            float4 w = wr[k4];
            const float* h4 = &S->hs[4 * k4];
            acc += w.x * h4[0] + w.y * h4[1] + w.z * h4[2] + w.w * h4[3];
        }
        g_y[b * 256 + tid] = acc;
        __syncthreads();
    }
    grid_sync(gen);

    // ================= BatchNorm over batch axis =================
    // block handles columns 2*bid, 2*bid+1; thread = batch row
    float* red = S->hs;
    for (int r = 0; r < 2; r++) {
        int j = 2 * bid + r;
        float v = g_y[tid * 256 + j];
        red[tid] = v;
        __syncthreads();
        for (int s = 128; s > 0; s >>= 1) {
            if (tid < s) red[tid] += red[tid + s];
            __syncthreads();
        }
        float mean = red[0] * (1.f / 256.f);
        __syncthreads();
        float d = v - mean;
        red[tid] = d * d;
        __syncthreads();
        for (int s = 128; s > 0; s >>= 1) {
            if (tid < s) red[tid] += red[tid + s];
            __syncthreads();
        }
        float var = red[0] * (1.f / 256.f);
        __syncthreads();
        out[tid * 256 + j] = bn_g[j] * d * rsqrtf(var + 1e-5f) + bn_b[j];
    }
}

// ---------------- launch ----------------
extern "C" void kernel_launch(void* const* d_in, const int* in_sizes, int n_in,
                              void* d_out, int out_size) {
    const int*   tokens    = (const int*)d_in[0];
    const int*   lengths   = (const int*)d_in[1];
    const float* embedding = (const float*)d_in[2];
    const float* w_ih0     = (const float*)d_in[3];
    const float* w_hh0     = (const float*)d_in[4];
    const float* b_ih0     = (const float*)d_in[5];
    const float* b_hh0     = (const float*)d_in[6];
    const float* w_ih1     = (const float*)d_in[7];
    const float* w_hh1     = (const float*)d_in[8];
    const float* b_ih1     = (const float*)d_in[9];
    const float* b_hh1     = (const float*)d_in[10];
    const float* ff_w      = (const float*)d_in[11];
    const float* ff_b      = (const float*)d_in[12];
    const float* bn_g      = (const float*)d_in[13];
    const float* bn_b      = (const float*)d_in[14];
    float* out = (float*)d_out;

    cudaFuncSetAttribute(lstm_kernel, cudaFuncAttributeMaxDynamicSharedMemorySize,
                         (int)sizeof(SmemLayout));

    prep_kernel<<<256, 256>>>(tokens, embedding);
    lstm_kernel<<<NBLK, TPB, sizeof(SmemLayout)>>>(
        lengths, w_ih0, w_hh0, b_ih0, b_hh0,
        w_ih1, w_hh1, b_ih1, b_hh1,
        ff_w, ff_b, bn_g, bn_b, out);
}

// round 3
// speedup vs baseline: 1.8426x; 1.8387x over previous
#include <cuda_runtime.h>
#include <math.h>

#define NBLK 128
#define TPB  128
typedef unsigned long long ull;

// ---------------- device scratch ----------------
__device__ float g_h1[2][256 * 256];   // [u][b]
__device__ float g_h2[2][256 * 256];   // [u][b]
__device__ float g_last[256 * 256];    // [b][u]
__device__ float g_y[256 * 256];       // [b][j]
__device__ float g_emb[256 * 256 * 8]; // [t][b][e]
__device__ unsigned g_bar;

struct SmemLayout {
    float Wh0[256 * 32];   // [k][c], c = unit*4 + gate
    float Wi1[256 * 32];
    float Wh1[256 * 32];
    float Wi0[8 * 32];
    float b0[32];
    float b1[32];
    float hsA[256 * 64];   // staged h [k][b_local]
    float hsB[256 * 64];
};

// ---------------- packed f32x2 helpers ----------------
__device__ __forceinline__ ull pk(float a, float b) {
    ull r; asm("mov.b64 %0, {%1,%2};" : "=l"(r) : "f"(a), "f"(b)); return r;
}
__device__ __forceinline__ void unpk(ull v, float& a, float& b) {
    asm("mov.b64 {%0,%1}, %2;" : "=f"(a), "=f"(b) : "l"(v));
}
__device__ __forceinline__ void fma2(ull& acc, ull a, ull b) {
    asm("fma.rn.f32x2 %0, %1, %2, %0;" : "+l"(acc) : "l"(a), "l"(b));
}

__device__ __forceinline__ float sigf(float x) { return 1.f / (1.f + __expf(-x)); }
__device__ __forceinline__ float tanha(float x) { return 2.f * sigf(2.f * x) - 1.f; }

// ---------------- grid barrier ----------------
__device__ __forceinline__ void grid_sync(unsigned& gen) {
    __syncthreads();
    if (threadIdx.x == 0) {
        __threadfence();
        atomicAdd(&g_bar, 1u);
        gen += NBLK;
        unsigned v;
        do {
            asm volatile("ld.acquire.gpu.global.u32 %0, [%1];" : "=r"(v) : "l"(&g_bar));
        } while (v < gen);
    }
    __syncthreads();
}

// ---------------- cp.async helpers ----------------
__device__ __forceinline__ void cpa16(float* dst_smem, const float* src) {
    unsigned d = (unsigned)__cvta_generic_to_shared(dst_smem);
    asm volatile("cp.async.cg.shared.global [%0], [%1], 16;" :: "r"(d), "l"(src));
}
__device__ __forceinline__ void cpa_commit() { asm volatile("cp.async.commit_group;"); }
#define CPA_WAIT(N) asm volatile("cp.async.wait_group %0;" :: "n"(N))

// stage: global [u][b] slice (cols bg*64..bg*64+63, all 256 u) -> smem [k][64]
__device__ __forceinline__ void stage_cg(float* __restrict__ hs,
                                         const float* __restrict__ src,
                                         int bg, int tid) {
    const float* base = src + bg * 64;
#pragma unroll
    for (int i = 0; i < 32; i++) {
        int idx = i * 128 + tid;        // 4096 float4 total
        int k = idx >> 4;
        int seg = (idx & 15) * 4;
        cpa16(hs + k * 64 + seg, base + k * 256 + seg);
    }
}

// ---------------- tile GEMM: thread = 4 rows x 1 unit (4 gate cols) ----------------
__device__ __forceinline__ void gemm8(const float* __restrict__ sW,
                                      const float* __restrict__ hs,
                                      int txc, int txb, ull acc[8]) {
    const float4* wp = (const float4*)(sW + 4 * txc);  // stride 8 float4 per k
    const float4* hp = (const float4*)(hs + 4 * txb);  // stride 16 float4 per k
#pragma unroll 8
    for (int k = 0; k < 256; k++) {
        float4 w = wp[k * 8];
        float4 h = hp[k * 16];
        ull w01 = pk(w.x, w.y), w23 = pk(w.z, w.w);
        ull d0 = pk(h.x, h.x), d1 = pk(h.y, h.y);
        ull d2 = pk(h.z, h.z), d3 = pk(h.w, h.w);
        fma2(acc[0], w01, d0); fma2(acc[1], w23, d0);
        fma2(acc[2], w01, d1); fma2(acc[3], w23, d1);
        fma2(acc[4], w01, d2); fma2(acc[5], w23, d2);
        fma2(acc[6], w01, d3); fma2(acc[7], w23, d3);
    }
}

__device__ __forceinline__ float lstm_h(ull g01, ull g23, float& cs) {
    float iv, fv, gv, ov;
    unpk(g01, iv, fv); unpk(g23, gv, ov);
    cs = sigf(fv) * cs + sigf(iv) * tanha(gv);
    return sigf(ov) * tanha(cs);
}

// ---------------- prep: embedding gather + barrier reset ----------------
__global__ void prep_kernel(const int* __restrict__ tokens,
                            const float* __restrict__ emb) {
    int idx = blockIdx.x * 256 + threadIdx.x;  // 0..65535
    if (idx == 0) g_bar = 0;
    int b = idx >> 8, t = idx & 255;
    int tok = tokens[b * 256 + t];
    const float4* e = (const float4*)(emb + tok * 8);
    float4* d = (float4*)(g_emb + (t * 256 + b) * 8);
    d[0] = e[0];
    d[1] = e[1];
}

// ---------------- persistent LSTM kernel ----------------
extern __shared__ float smem_raw[];

__global__ void __launch_bounds__(TPB, 1)
lstm_kernel(const int* __restrict__ lengths,
            const float* __restrict__ w_ih0, const float* __restrict__ w_hh0,
            const float* __restrict__ b_ih0, const float* __restrict__ b_hh0,
            const float* __restrict__ w_ih1, const float* __restrict__ w_hh1,
            const float* __restrict__ b_ih1, const float* __restrict__ b_hh1,
            const float* __restrict__ ff_w, const float* __restrict__ ff_b,
            const float* __restrict__ bn_g, const float* __restrict__ bn_b,
            float* __restrict__ out) {
    SmemLayout* S = (SmemLayout*)smem_raw;
    const int tid = threadIdx.x;
    const int bid = blockIdx.x;
    const int bg = bid >> 5;    // batch group 0..3 (64 rows)
    const int ug = bid & 31;    // unit group 0..31 (8 units)
    const int txc = tid & 7;    // unit within group
    const int txb = tid >> 3;   // 0..15 -> rows 4*txb..4*txb+3
    const int rb = bg * 64 + 4 * txb;   // first batch row
    const int u = ug * 8 + txc;

    // --- load + permute weights into SMEM ---
    for (int idx = tid; idx < 32 * 256; idx += TPB) {
        int c = idx & 31, k = idx >> 5;
        int uu = c >> 2, g = c & 3;
        int row = g * 256 + ug * 8 + uu;
        S->Wh0[k * 32 + c] = w_hh0[row * 256 + k];
        S->Wi1[k * 32 + c] = w_ih1[row * 256 + k];
        S->Wh1[k * 32 + c] = w_hh1[row * 256 + k];
    }
    for (int idx = tid; idx < 8 * 32; idx += TPB) {
        int c = idx & 31, e = idx >> 5;
        int uu = c >> 2, g = c & 3;
        int row = g * 256 + ug * 8 + uu;
        S->Wi0[e * 32 + c] = w_ih0[row * 8 + e];
    }
    if (tid < 32) {
        int uu = tid >> 2, g = tid & 3;
        int row = g * 256 + ug * 8 + uu;
        S->b0[tid] = b_ih0[row] + b_hh0[row];
        S->b1[tid] = b_ih1[row] + b_hh1[row];
    }
    // zero initial state buffers (parity 1 is read at t=0)
    float4 z4 = make_float4(0.f, 0.f, 0.f, 0.f);
    *(float4*)(&g_h1[1][u * 256 + rb]) = z4;
    *(float4*)(&g_h2[1][u * 256 + rb]) = z4;

    int4 ln4 = *(const int4*)(lengths + rb);
    int ln[4] = {ln4.x, ln4.y, ln4.z, ln4.w};
    float c1s[4] = {0.f, 0.f, 0.f, 0.f};
    float c2s[4] = {0.f, 0.f, 0.f, 0.f};
    unsigned gen = 0;
    grid_sync(gen);

    // prefetch initial h1 (zeros) into P
    float* P = S->hsA;
    float* Q = S->hsB;
    stage_cg(P, g_h1[1], bg, tid);
    cpa_commit();

    ull bi01_0 = pk(S->b0[4 * txc + 0], S->b0[4 * txc + 1]);
    ull bi23_0 = pk(S->b0[4 * txc + 2], S->b0[4 * txc + 3]);
    ull bi01_1 = pk(S->b1[4 * txc + 0], S->b1[4 * txc + 1]);
    ull bi23_1 = pk(S->b1[4 * txc + 2], S->b1[4 * txc + 3]);

    for (int t = 0; t < 256; t++) {
        const int wpar = t & 1;         // write parity
        const int rpar = wpar ^ 1;      // read parity (prev step)

        CPA_WAIT(0);
        __syncthreads();                // P holds h1(t-1)

        // ================= layer 0 =================
        ull a[8];
        a[0] = a[2] = a[4] = a[6] = bi01_0;
        a[1] = a[3] = a[5] = a[7] = bi23_0;
        {
            // x-part: emb [t][b][8], 4 rows contiguous = 32 floats
            const float4* ep = (const float4*)(g_emb + (t * 256 + rb) * 8);
            float xv[4][8];
#pragma unroll
            for (int r = 0; r < 4; r++) {
                float4 u0 = ep[2 * r], u1 = ep[2 * r + 1];
                xv[r][0] = u0.x; xv[r][1] = u0.y; xv[r][2] = u0.z; xv[r][3] = u0.w;
                xv[r][4] = u1.x; xv[r][5] = u1.y; xv[r][6] = u1.z; xv[r][7] = u1.w;
            }
#pragma unroll
            for (int e = 0; e < 8; e++) {
                float4 w = *(const float4*)(&S->Wi0[e * 32 + 4 * txc]);
                ull w01 = pk(w.x, w.y), w23 = pk(w.z, w.w);
#pragma unroll
                for (int r = 0; r < 4; r++) {
                    ull xd = pk(xv[r][e], xv[r][e]);
                    fma2(a[2 * r], w01, xd);
                    fma2(a[2 * r + 1], w23, xd);
                }
            }
        }
        gemm8(S->Wh0, P, txc, txb, a);

        float h1v[4];
#pragma unroll
        for (int r = 0; r < 4; r++)
            h1v[r] = lstm_h(a[2 * r], a[2 * r + 1], c1s[r]);
        *(float4*)(&g_h1[wpar][u * 256 + rb]) = make_float4(h1v[0], h1v[1], h1v[2], h1v[3]);

        grid_sync(gen);   // the ONLY barrier per step

        // ================= layer 1 =================
        stage_cg(Q, g_h1[wpar], bg, tid);   // h1(t)     group 0
        cpa_commit();
        stage_cg(P, g_h2[rpar], bg, tid);   // h2(t-1)   group 1
        cpa_commit();

        a[0] = a[2] = a[4] = a[6] = bi01_1;
        a[1] = a[3] = a[5] = a[7] = bi23_1;

        CPA_WAIT(1);
        __syncthreads();                    // Q ready
        gemm8(S->Wi1, Q, txc, txb, a);

        CPA_WAIT(0);
        __syncthreads();                    // P ready
        gemm8(S->Wh1, P, txc, txb, a);

        float h2v[4];
#pragma unroll
        for (int r = 0; r < 4; r++)
            h2v[r] = lstm_h(a[2 * r], a[2 * r + 1], c2s[r]);
        *(float4*)(&g_h2[wpar][u * 256 + rb]) = make_float4(h2v[0], h2v[1], h2v[2], h2v[3]);
#pragma unroll
        for (int r = 0; r < 4; r++)
            if (t == ln[r] - 1) g_last[(rb + r) * 256 + u] = h2v[r];

        // Q now holds h1(t) = next step's L0 input: swap roles
        float* tmp = P; P = Q; Q = tmp;
    }

    grid_sync(gen);

    // ================= y = relu(last) @ ff_w^T + ff_b =================
    // block handles batch rows 2*bid, 2*bid+1; thread = cols tid, tid+128
    {
        float* sv = S->hsA;
        int br0 = 2 * bid, br1 = 2 * bid + 1;
        sv[tid]           = fmaxf(g_last[br0 * 256 + tid], 0.f);
        sv[tid + 128]     = fmaxf(g_last[br0 * 256 + tid + 128], 0.f);
        sv[256 + tid]     = fmaxf(g_last[br1 * 256 + tid], 0.f);
        sv[256 + tid + 128] = fmaxf(g_last[br1 * 256 + tid + 128], 0.f);
        __syncthreads();
        int j0 = tid, j1 = tid + 128;
        float a00 = ff_b[j0], a01 = ff_b[j1];
        float a10 = a00, a11 = a01;
        const float4* w0 = (const float4*)(ff_w + j0 * 256);
        const float4* w1 = (const float4*)(ff_w + j1 * 256);
        const float4* h0 = (const float4*)sv;
        const float4* h1 = (const float4*)(sv + 256);
#pragma unroll 4
        for (int k4 = 0; k4 < 64; k4++) {
            float4 wa = w0[k4], wb = w1[k4];
            float4 ha = h0[k4], hb = h1[k4];
            a00 += wa.x * ha.x + wa.y * ha.y + wa.z * ha.z + wa.w * ha.w;
            a10 += wa.x * hb.x + wa.y * hb.y + wa.z * hb.z + wa.w * hb.w;
            a01 += wb.x * ha.x + wb.y * ha.y + wb.z * ha.z + wb.w * ha.w;
            a11 += wb.x * hb.x + wb.y * hb.y + wb.z * hb.z + wb.w * hb.w;
        }
        g_y[br0 * 256 + j0] = a00; g_y[br0 * 256 + j1] = a01;
        g_y[br1 * 256 + j0] = a10; g_y[br1 * 256 + j1] = a11;
    }

    grid_sync(gen);

    // ================= BatchNorm over batch axis =================
    // block handles cols 2*bid, 2*bid+1; thread = batch rows tid, tid+128
    {
        float* red = S->hsA;
        for (int r = 0; r < 2; r++) {
            int j = 2 * bid + r;
            float v0 = g_y[tid * 256 + j];
            float v1 = g_y[(tid + 128) * 256 + j];
            __syncthreads();
            red[tid] = v0 + v1;
            __syncthreads();
            for (int s = 64; s > 0; s >>= 1) {
                if (tid < s) red[tid] += red[tid + s];
                __syncthreads();
            }
            float mean = red[0] * (1.f / 256.f);
            __syncthreads();
            float d0 = v0 - mean, d1 = v1 - mean;
            red[tid] = d0 * d0 + d1 * d1;
            __syncthreads();
            for (int s = 64; s > 0; s >>= 1) {
                if (tid < s) red[tid] += red[tid + s];
                __syncthreads();
            }
            float inv = rsqrtf(red[0] * (1.f / 256.f) + 1e-5f);
            __syncthreads();
            float gm = bn_g[j], bt = bn_b[j];
            out[tid * 256 + j]         = gm * d0 * inv + bt;
            out[(tid + 128) * 256 + j] = gm * d1 * inv + bt;
        }
    }
}

// ---------------- launch ----------------
extern "C" void kernel_launch(void* const* d_in, const int* in_sizes, int n_in,
                              void* d_out, int out_size) {
    const int*   tokens    = (const int*)d_in[0];
    const int*   lengths   = (const int*)d_in[1];
    const float* embedding = (const float*)d_in[2];
    const float* w_ih0     = (const float*)d_in[3];
    const float* w_hh0     = (const float*)d_in[4];
    const float* b_ih0     = (const float*)d_in[5];
    const float* b_hh0     = (const float*)d_in[6];
    const float* w_ih1     = (const float*)d_in[7];
    const float* w_hh1     = (const float*)d_in[8];
    const float* b_ih1     = (const float*)d_in[9];
    const float* b_hh1     = (const float*)d_in[10];
    const float* ff_w      = (const float*)d_in[11];
    const float* ff_b      = (const float*)d_in[12];
    const float* bn_g      = (const float*)d_in[13];
    const float* bn_b      = (const float*)d_in[14];
    float* out = (float*)d_out;

    cudaFuncSetAttribute(lstm_kernel, cudaFuncAttributeMaxDynamicSharedMemorySize,
                         (int)sizeof(SmemLayout));

    prep_kernel<<<256, 256>>>(tokens, embedding);
    lstm_kernel<<<NBLK, TPB, sizeof(SmemLayout)>>>(
        lengths, w_ih0, w_hh0, b_ih0, b_hh0,
        w_ih1, w_hh1, b_ih1, b_hh1,
        ff_w, ff_b, bn_g, bn_b, out);
}